// round 4
// baseline (speedup 1.0000x reference)
#include <cuda_runtime.h>
#include <cstdint>

#define POOL 7
#define NUM_ROIS 512
#define IMG_W 128
#define CH 1024
#define N_CELLS (NUM_ROIS * POOL * POOL)   // 25088
#define F4_PER_CELL (CH / 4)               // 256

// Precomputed per-cell params: corner offsets (in float4 units) + bilinear weights.
__device__ int4   g_offs[N_CELLS];
__device__ float4 g_wts[N_CELLS];

// ---------------- setup: one thread per cell ----------------
__global__ void roi_setup_kernel(const int* __restrict__ rois) {
    const int cell = blockIdx.x * blockDim.x + threadIdx.x;
    if (cell >= N_CELLS) return;

    const int roi = cell / (POOL * POOL);
    const int rem = cell - roi * (POOL * POOL);
    const int py  = rem / POOL;
    const int px  = rem - py * POOL;

    const int x = rois[roi * 4 + 0];
    const int y = rois[roi * 4 + 1];
    const int w = rois[roi * 4 + 2];
    const int h = rois[roi * 4 + 3];

    const float hf = (float)h;
    const float wf = (float)w;

    // half-pixel-center source coords, clamped (matches tf.image.resize bilinear)
    float ys = ((float)py + 0.5f) * hf * (1.0f / POOL) - 0.5f;
    float xs = ((float)px + 0.5f) * wf * (1.0f / POOL) - 0.5f;
    ys = fminf(fmaxf(ys, 0.0f), hf - 1.0f);
    xs = fminf(fmaxf(xs, 0.0f), wf - 1.0f);

    const int y0 = (int)floorf(ys);
    const int x0 = (int)floorf(xs);
    const int y1 = min(y0 + 1, h - 1);
    const int x1 = min(x0 + 1, w - 1);
    const float fy = ys - (float)y0;
    const float fx = xs - (float)x0;

    const int ay0 = y + y0, ay1 = y + y1;
    const int ax0 = x + x0, ax1 = x + x1;

    int4 off;
    off.x = (ay0 * IMG_W + ax0) * F4_PER_CELL;
    off.y = (ay0 * IMG_W + ax1) * F4_PER_CELL;
    off.z = (ay1 * IMG_W + ax0) * F4_PER_CELL;
    off.w = (ay1 * IMG_W + ax1) * F4_PER_CELL;
    g_offs[cell] = off;

    float4 wt;
    wt.x = (1.0f - fy) * (1.0f - fx);
    wt.y = (1.0f - fy) * fx;
    wt.z = fy * (1.0f - fx);
    wt.w = fy * fx;
    g_wts[cell] = wt;
}

// ---------------- main: 4 cells per 256-thread block ----------------
// 64 threads per cell; thread t covers f4 lanes t, t+64, t+128, t+192
// => 16 independent coalesced LDG.128 in flight per thread.
__global__ __launch_bounds__(256)
void roi_pool_kernel(const float* __restrict__ img,
                     float* __restrict__ out) {
    const int grp  = threadIdx.x >> 6;          // 0..3
    const int t    = threadIdx.x & 63;          // 0..63
    const int cell = blockIdx.x * 4 + grp;

    const int4   off = g_offs[cell];
    const float4 wt  = g_wts[cell];

    const float4* __restrict__ base = (const float4*)img;
    const float4* p00 = base + off.x + t;
    const float4* p01 = base + off.y + t;
    const float4* p10 = base + off.z + t;
    const float4* p11 = base + off.w + t;

    float4 a[4], b[4], c[4], d[4];
#pragma unroll
    for (int j = 0; j < 4; j++) a[j] = __ldg(p00 + j * 64);
#pragma unroll
    for (int j = 0; j < 4; j++) b[j] = __ldg(p01 + j * 64);
#pragma unroll
    for (int j = 0; j < 4; j++) c[j] = __ldg(p10 + j * 64);
#pragma unroll
    for (int j = 0; j < 4; j++) d[j] = __ldg(p11 + j * 64);

    float4* o = (float4*)out + (size_t)cell * F4_PER_CELL + t;

#pragma unroll
    for (int j = 0; j < 4; j++) {
        float4 r;
        r.x = a[j].x * wt.x + b[j].x * wt.y + c[j].x * wt.z + d[j].x * wt.w;
        r.y = a[j].y * wt.x + b[j].y * wt.y + c[j].y * wt.z + d[j].y * wt.w;
        r.z = a[j].z * wt.x + b[j].z * wt.y + c[j].z * wt.z + d[j].z * wt.w;
        r.w = a[j].w * wt.x + b[j].w * wt.y + c[j].w * wt.z + d[j].w * wt.w;
        __stcs(o + j * 64, r);   // streaming store: keep image resident in L2
    }
}

extern "C" void kernel_launch(void* const* d_in, const int* in_sizes, int n_in,
                              void* d_out, int out_size) {
    const float* img  = (const float*)d_in[0];
    const int*   rois = (const int*)d_in[1];
    float*       out  = (float*)d_out;

    roi_setup_kernel<<<(N_CELLS + 255) / 256, 256>>>(rois);
    roi_pool_kernel<<<N_CELLS / 4, 256>>>(img, out);
}